// round 15
// baseline (speedup 1.0000x reference)
#include <cuda_runtime.h>
#include <cstdint>

#define FFT_N 512
#define NBIN (FFT_N * FFT_N)
#define N_C 3
#define N_K 8
#define N_V 9
#define NIMG_X (N_C * N_K)   // 24
#define NIMG_Y (N_C * N_V)   // 27
#define NKX 257              // half-spectrum columns kept (kx in [0,256])
#define NHBIN (FFT_N * NKX)  // 131584 half-spectrum bins
#define PI_F 3.14159265358979323846f

// column-FFT kernels: 8 slices * 1156 floats (stride ≡ 4 mod 32 -> conflict-free
// for the c = tid&7 interleave in all four exchange phases; 36.1KB static smem)
#define CSTRIDE8 1156

// solve kernel staging: 51 planes * 128 threads * 8B = 52224 bytes dynamic smem
#define SOLVE_SMEM_BYTES ((NIMG_X + NIMG_Y) * 128 * 8)

// ---------------- scratch (static device globals; no cudaMalloc allowed) ----
__device__ float2 d_Xs[(size_t)NIMG_X * NBIN];   // X spectrum, reused as FDL spectrum
__device__ float2 d_Ys[(size_t)NIMG_Y * NBIN];   // Y spectrum
__device__ float2 d_tw[256];                     // W_512^j, j in [0,256)
__device__ float4 d_etab[FFT_N];                 // per-freq (exp(i*delta*w), exp(-i*d0*w))

// ---------------- complex helpers -------------------------------------------
__device__ __forceinline__ float2 cmulf2(float2 a, float2 b) {
    return make_float2(fmaf(a.x, b.x, -a.y * b.y), fmaf(a.x, b.y, a.y * b.x));
}
__device__ __forceinline__ float2 caddf2(float2 a, float2 b) { return make_float2(a.x + b.x, a.y + b.y); }
__device__ __forceinline__ float2 csubf2(float2 a, float2 b) { return make_float2(a.x - b.x, a.y - b.y); }
__device__ __forceinline__ float2 cconjf2(float2 a) { return make_float2(a.x, -a.y); }

__device__ __forceinline__ float2 cpowi(float2 z, float s) {
    if (s > 0.5f) return z;
    if (s < -0.5f) return cconjf2(z);
    return make_float2(1.f, 0.f);
}

// ---------------- packed f32x2 helpers (Blackwell FFMA2 via PTX) --------------
typedef unsigned long long u64p;
__device__ __forceinline__ u64p pk2(float x, float y) {
    u64p r; asm("mov.b64 %0, {%1, %2};" : "=l"(r) : "f"(x), "f"(y)); return r;
}
__device__ __forceinline__ u64p dup2(float s) { return pk2(s, s); }
__device__ __forceinline__ u64p fma2(u64p a, u64p b, u64p c) {
    u64p r; asm("fma.rn.f32x2 %0, %1, %2, %3;" : "=l"(r) : "l"(a), "l"(b), "l"(c)); return r;
}
__device__ __forceinline__ u64p mul2(u64p a, u64p b) {
    u64p r; asm("mul.rn.f32x2 %0, %1, %2;" : "=l"(r) : "l"(a), "l"(b)); return r;
}

// ---------------- cp.async helpers --------------------------------------------
__device__ __forceinline__ uint32_t smem_u32(const void* p) {
    uint32_t a;
    asm("{ .reg .u64 t; cvta.to.shared.u64 t, %1; cvt.u32.u64 %0, t; }" : "=r"(a) : "l"(p));
    return a;
}
__device__ __forceinline__ void cp_async8(uint32_t dst, const void* src) {
    asm volatile("cp.async.ca.shared.global [%0], [%1], 8;" :: "r"(dst), "l"(src));
}

// ---------------- table fill -------------------------------------------------
__global__ void fill_tables(const float* __restrict__ dp) {
    int j = threadIdx.x;
    if (j < 256) {
        float ang = -2.f * PI_F * (float)j / (float)FFT_N;
        float s, c;
        sincosf(ang, &s, &c);
        d_tw[j] = make_float2(c, s);
    }
    if (j < FFT_N) {
        float cf = (j < FFT_N / 2) ? (float)j : (float)(j - FFT_N);  // centered freq index
        float w = cf * (2.f * PI_F / (float)FFT_N);
        float delta = dp[1] - dp[0];
        float d0 = dp[0];
        float s1, c1, s2, c2;
        sincosf(delta * w, &s1, &c1);   // exp(+i*delta*w)
        sincosf(-d0 * w, &s2, &c2);     // exp(-i*d0*w)
        d_etab[j] = make_float4(c1, s1, c2, s2);
    }
}

// ---------------- register radix-8 butterflies --------------------------------
template <int INV>
__device__ __forceinline__ void fft4x(float2 v[4]) {
    float2 e0 = caddf2(v[0], v[2]), e1 = caddf2(v[1], v[3]);
    float2 o0 = csubf2(v[0], v[2]), o1 = csubf2(v[1], v[3]);
    o1 = INV ? make_float2(-o1.y, o1.x) : make_float2(o1.y, -o1.x);  // *(+-i)
    v[0] = caddf2(e0, e1); v[2] = csubf2(e0, e1);
    v[1] = caddf2(o0, o1); v[3] = csubf2(o0, o1);
}

template <int INV>
__device__ __forceinline__ void fft8(float2 a[8]) {
    const float C = 0.70710678118654752440f;
    float2 s[4], d[4];
#pragma unroll
    for (int k = 0; k < 4; k++) { s[k] = caddf2(a[k], a[k + 4]); d[k] = csubf2(a[k], a[k + 4]); }
    if (INV) {
        d[1] = cmulf2(d[1], make_float2(C, C));
        d[2] = make_float2(-d[2].y, d[2].x);
        d[3] = cmulf2(d[3], make_float2(-C, C));
    } else {
        d[1] = cmulf2(d[1], make_float2(C, -C));
        d[2] = make_float2(d[2].y, -d[2].x);
        d[3] = cmulf2(d[3], make_float2(-C, -C));
    }
    fft4x<INV>(s);
    fft4x<INV>(d);
    a[0] = s[0]; a[2] = s[1]; a[4] = s[2]; a[6] = s[3];
    a[1] = d[0]; a[3] = d[1]; a[5] = d[2]; a[7] = d[3];
}

// ---------------- 512-pt FFT: 64 threads, 8 regs, single-buffer (3 syncs) -----
// In:  a[j]  = x[t + 64*j],  t in [0,64)
// Out: a[m1] = X[t + 64*m1]
// Exchange A layout: [k0*72 + t]          Exchange B layout: [9*k0 + 72*m0 + r]
template <int INV>
__device__ __forceinline__ void fft512r8(float2 a[8], int t, float* re, float* im) {
    fft8<INV>(a);
    {   // a[k0] *= W512^{t*k0}
        float2 w = d_tw[t]; if (INV) w.y = -w.y;
        float2 p = w;
#pragma unroll
        for (int k = 1; k < 8; k++) { a[k] = cmulf2(a[k], p); p = cmulf2(p, w); }
    }
#pragma unroll
    for (int k = 0; k < 8; k++) { re[k * 72 + t] = a[k].x; im[k * 72 + t] = a[k].y; }
    __syncthreads();
    int hi = t >> 3, lo = t & 7;
#pragma unroll
    for (int j = 0; j < 8; j++) {
        int idx = hi * 72 + 8 * j + lo;
        a[j] = make_float2(re[idx], im[idx]);
    }
    __syncthreads();                               // all reads done before overwrite
    fft8<INV>(a);
    {   // a[m0] *= W64^{lo*m0} = W512^{8*lo*m0}
        float2 w = d_tw[8 * lo]; if (INV) w.y = -w.y;
        float2 p = w;
#pragma unroll
        for (int m = 1; m < 8; m++) { a[m] = cmulf2(a[m], p); p = cmulf2(p, w); }
    }
#pragma unroll
    for (int m = 0; m < 8; m++) {
        int idx = 9 * hi + 72 * m + lo;
        re[idx] = a[m].x; im[idx] = a[m].y;
    }
    __syncthreads();
#pragma unroll
    for (int r = 0; r < 8; r++) {
        int idx = 9 * lo + 72 * hi + r;
        a[r] = make_float2(re[idx], im[idx]);
    }
    fft8<INV>(a);
}

// ---------------- row FFT, PAIRED: two real rows per complex FFT --------------
// z = row(2p) + i*row(2p+1); A(k) = (Z(k)+conj(Z(-k)))/2, B(k) = (Z(k)-conj(Z(-k)))/2i.
// One block = 4 sub-FFTs = 4 row pairs = 8 rows. X and Y planes in one launch.
__global__ void fwd_rows_all(const float* __restrict__ xin, const float* __restrict__ yin) {
    __shared__ float s[4 * 1160];
    int blk = blockIdx.x;
    const float* in;
    float2* outp;
    if (blk < NIMG_X * (FFT_N / 8)) { in = xin; outp = d_Xs; }
    else { blk -= NIMG_X * (FFT_N / 8); in = yin; outp = d_Ys; }
    int sub = threadIdx.x >> 6;
    int t = threadIdx.x & 63;
    size_t pair = (size_t)blk * 4 + sub;           // row-pair index (512 rows/plane, 8|512)
    const float* src0 = in + pair * 2 * FFT_N;
    const float* src1 = src0 + FFT_N;
    float2* dst0 = outp + pair * 2 * FFT_N;
    float2* dst1 = dst0 + FFT_N;
    float2 a[8];
#pragma unroll
    for (int j = 0; j < 8; j++) a[j] = make_float2(src0[t + 64 * j], src1[t + 64 * j]);
    float* base = s + sub * 1160;
    fft512r8<0>(a, t, base, base + 576);
    // stash full Z in the (now free) exchange buffer for mirror access
    float2* zb = (float2*)base;                    // 580 c64 capacity >= 512
    __syncthreads();
#pragma unroll
    for (int m = 0; m < 8; m++) zb[t + 64 * m] = a[m];
    __syncthreads();
#pragma unroll
    for (int m = 0; m < 8; m++) {
        int k = t + 64 * m;
        if (k < NKX) {
            float2 Z = a[m];
            float2 Zm = zb[(512 - k) & 511];
            dst0[k] = make_float2(0.5f * (Z.x + Zm.x), 0.5f * (Z.y - Zm.y));   // A(k)
            dst1[k] = make_float2(0.5f * (Z.y + Zm.y), -0.5f * (Z.x - Zm.x));  // B(k)
        }
    }
}

// ---------------- forward column FFT: 8 columns per 512-thread block ----------
// Warp covers 8 consecutive kx x 4 rows = four full 128B lines per global op.
// 4 blocks/SM (36.1KB static smem), 16-warp barriers. X and Y in one launch.
__global__ void __launch_bounds__(512, 4) fft_cols_fwd(void) {
    __shared__ float s[8 * CSTRIDE8];
    int p = blockIdx.y;
    float2* data = (p < NIMG_X) ? d_Xs + (size_t)p * NBIN
                                : d_Ys + (size_t)(p - NIMG_X) * NBIN;
    int c = threadIdx.x & 7;
    int t = threadIdx.x >> 3;         // [0,64)
    int kx = blockIdx.x * 8 + c;
    bool act = (kx < NKX);
    float2* col = data + kx;
    float2 a[8];
#pragma unroll
    for (int j = 0; j < 8; j++)
        a[j] = act ? col[(size_t)(t + 64 * j) * FFT_N] : make_float2(0.f, 0.f);
    float* base = s + c * CSTRIDE8;
    fft512r8<0>(a, t, base, base + 576);
#pragma unroll
    for (int m = 0; m < 8; m++)
        if (act) col[(size_t)(t + 64 * m) * FFT_N] = a[m];
}

// ---------------- inverse column FFT (X planes), 8 columns/block --------------
__global__ void __launch_bounds__(512, 4) fft_cols_inv(void) {
    __shared__ float s[8 * CSTRIDE8];
    float2* data = d_Xs + (size_t)blockIdx.y * NBIN;
    int c = threadIdx.x & 7;
    int t = threadIdx.x >> 3;
    int kx = blockIdx.x * 8 + c;
    bool act = (kx < NKX);
    float2* col = data + kx;
    float2 a[8];
#pragma unroll
    for (int j = 0; j < 8; j++)
        a[j] = act ? col[(size_t)(t + 64 * j) * FFT_N] : make_float2(0.f, 0.f);
    float* base = s + c * CSTRIDE8;
    fft512r8<1>(a, t, base, base + 576);
#pragma unroll
    for (int m = 0; m < 8; m++)
        if (act) col[(size_t)(t + 64 * m) * FFT_N] = a[m];
}

// ---------------- inverse row FFT, PAIRED: two real rows per complex IFFT -----
__global__ void inv_rows(float* __restrict__ out) {
    __shared__ float s[4 * 1160];
    int sub = threadIdx.x >> 6;
    int t = threadIdx.x & 63;
    size_t pair = (size_t)blockIdx.x * 4 + sub;
    const float2* src0 = d_Xs + pair * 2 * FFT_N;
    const float2* src1 = src0 + FFT_N;
    float* dst0 = out + pair * 2 * FFT_N;
    float* dst1 = dst0 + FFT_N;
    float2 a[8];
#pragma unroll
    for (int j = 0; j < 8; j++) {
        int k = t + 64 * j;
        float2 Sa, Sb;
        if (k < NKX) {
            Sa = src0[k]; Sb = src1[k];
            if (k == 0 || k == 256) { Sa.y = 0.f; Sb.y = 0.f; }   // self-mirror cleanup
        } else {
            float2 ma = src0[512 - k], mb = src1[512 - k];
            Sa = make_float2(ma.x, -ma.y);
            Sb = make_float2(mb.x, -mb.y);
        }
        a[j] = make_float2(Sa.x - Sb.y, Sa.y + Sb.x);              // H_a + i*H_b
    }
    float* base = s + sub * 1160;
    fft512r8<1>(a, t, base, base + 576);
    const float sc = 1.f / (float)NBIN;
#pragma unroll
    for (int m = 0; m < 8; m++) {
        dst0[t + 64 * m] = a[m].x * sc;
        dst1[t + 64 * m] = a[m].y * sc;
    }
}

// ---------------- per-bin FDL solve: cp.async staged, Cholesky-overlapped ------
// One thread = one bin. All 51 plane values stream into shared via cp.async
// (full MLP, zero register cost) WHILE the thread computes tmr + the real
// Toeplitz Cholesky (registers, R12 structure). After wait_group, rhs math
// reads shared ([plane][tid] layout, conflict-free, own-slot so no barrier).
// Row (ky==256, kx in [1,255]): conjugate y-exponentials, scale result by 0.5.
__global__ void __launch_bounds__(128, 4) solve_kernel(const float* __restrict__ up,
                                                       const float* __restrict__ vp,
                                                       const float* __restrict__ rhop) {
    extern __shared__ float2 sbuf[];               // [51][128]: X planes then Y planes
    int tid = threadIdx.x;
    int bidx = blockIdx.x * blockDim.x + tid;      // half-spectrum bin index
    int ky = bidx / NKX;
    int kx = bidx - ky * NKX;
    int bin = ky * FFT_N + kx;

    // fire all 51 async copies up front (8B each; per-thread slot)
    {
        uint32_t dst = smem_u32(&sbuf[tid]);
#pragma unroll
        for (int i = 0; i < NIMG_X; i++)
            cp_async8(dst + (uint32_t)i * 128 * 8, &d_Xs[(size_t)i * NBIN + bin]);
#pragma unroll
        for (int i = 0; i < NIMG_Y; i++)
            cp_async8(dst + (uint32_t)(NIMG_X + i) * 128 * 8, &d_Ys[(size_t)i * NBIN + bin]);
        asm volatile("cp.async.commit_group;");
    }

    float rho = rhop[0];
    float4 ex = d_etab[kx];
    float4 ey = d_etab[ky];
    float2 Edx = make_float2(ex.x, ex.y), E0x = make_float2(ex.z, ex.w);
    float2 Edy = make_float2(ey.x, ey.y), E0y = make_float2(ey.z, ey.w);

    bool mirror_row = (ky == 256 && kx >= 1 && kx <= 255);
    float hsc = mirror_row ? 0.5f : 1.0f;
    if (mirror_row) { Edy = cconjf2(Edy); E0y = cconjf2(E0y); }   // wy: -pi -> +pi

    // real Toeplitz generators t[m] = (1+2cos(m d wx))(1+2cos(m d wy))
    float tmr[8];
    {
        float axc = Edx.x, ayc = Edy.x;
        float cx1 = 1.f, cx = axc;
        float cy1 = 1.f, cy = ayc;
#pragma unroll
        for (int m = 1; m < 8; m++) {
            tmr[m] = (1.f + 2.f * cx) * (1.f + 2.f * cy);
            float nx = fmaf(2.f * axc, cx, -cx1); cx1 = cx; cx = nx;
            float ny = fmaf(2.f * ayc, cy, -cy1); cy1 = cy; cy = ny;
        }
    }

    // real Cholesky (diag = 9 + rho, off-diag t[|k-l|]) -- overlaps the copies
    float L[8][8];
    float di[8];
#pragma unroll
    for (int l = 0; l < 8; l++) {
        float ds = (float)N_V + rho;
#pragma unroll
        for (int j = 0; j < l; j++) ds = fmaf(-L[l][j], L[l][j], ds);
        float inv = rsqrtf(ds);
        di[l] = inv;
#pragma unroll
        for (int k = l + 1; k < 8; k++) {
            float s = tmr[k - l];
#pragma unroll
            for (int j = 0; j < l; j++) s = fmaf(-L[k][j], L[l][j], s);
            L[k][l] = s * inv;
        }
    }

    asm volatile("cp.async.wait_group 0;" ::: "memory");

    // rhs = rho*X (from staged shared)
    u64p rhs[N_C][N_K];
    {
        u64p rho2 = dup2(rho);
#pragma unroll
        for (int c = 0; c < N_C; c++)
#pragma unroll
            for (int k = 0; k < N_K; k++) {
                float2 xv = sbuf[(c * N_K + k) * 128 + tid];
                rhs[c][k] = mul2(pk2(xv.x, xv.y), rho2);
            }
    }

    // accumulate A^H Y (Y from staged shared; FFMA2 pairs)
#pragma unroll
    for (int vi = 0; vi < N_V; vi++) {
        float uu = up[vi], vv = vp[vi];
        float2 e  = cmulf2(cpowi(Edx, uu), cpowi(Edy, vv));   // exp(+i*delta*s_v)
        float2 e0 = cmulf2(cpowi(E0x, uu), cpowi(E0y, vv));   // exp(-i*d0*s_v)
        float2 ec = cconjf2(e);

        u64p yp[N_C], ys[N_C];
#pragma unroll
        for (int c = 0; c < N_C; c++) {
            float2 yv = sbuf[(NIMG_X + c * N_V + vi) * 128 + tid];
            yp[c] = pk2(yv.x, yv.y);
            ys[c] = pk2(-yv.y, yv.x);
        }

        float2 ak = e0;    // conj(A[v,k]) power chain (scalar)
#pragma unroll
        for (int k = 0; k < N_K; k++) {
            u64p axd = dup2(ak.x);
            u64p ayd = dup2(ak.y);
#pragma unroll
            for (int c = 0; c < N_C; c++)
                rhs[c][k] = fma2(axd, yp[c], fma2(ayd, ys[c], rhs[c][k]));
            ak = cmulf2(ak, ec);
        }
    }

    // forward substitution (channel-inner: dup(-L) shared across channels)
#pragma unroll
    for (int l = 0; l < 8; l++) {
#pragma unroll
        for (int j = 0; j < l; j++) {
            u64p Ld = dup2(-L[l][j]);
#pragma unroll
            for (int c = 0; c < N_C; c++)
                rhs[c][l] = fma2(Ld, rhs[c][j], rhs[c][l]);
        }
        u64p dd = dup2(di[l]);
#pragma unroll
        for (int c = 0; c < N_C; c++) rhs[c][l] = mul2(rhs[c][l], dd);
    }
    // back substitution
#pragma unroll
    for (int k = 7; k >= 0; k--) {
#pragma unroll
        for (int j = k + 1; j < 8; j++) {
            u64p Ld = dup2(-L[j][k]);
#pragma unroll
            for (int c = 0; c < N_C; c++)
                rhs[c][k] = fma2(Ld, rhs[c][j], rhs[c][k]);
        }
        u64p dd = dup2(di[k]);
#pragma unroll
        for (int c = 0; c < N_C; c++) rhs[c][k] = mul2(rhs[c][k], dd);
    }

    // store with mirror-row half-weight
    u64p hd = dup2(hsc);
#pragma unroll
    for (int c = 0; c < N_C; c++)
#pragma unroll
        for (int k = 0; k < N_K; k++)
            *(u64p*)&d_Xs[((size_t)(c * N_K + k)) * NBIN + bin] = mul2(rhs[c][k], hd);
}

// ---------------- launch ------------------------------------------------------
extern "C" void kernel_launch(void* const* d_in, const int* in_sizes, int n_in,
                              void* d_out, int out_size) {
    const float* x   = (const float*)d_in[0];  // [1,3,8,512,512]
    const float* y   = (const float*)d_in[1];  // [1,3,9,512,512]
    const float* u   = (const float*)d_in[2];  // [9]
    const float* v   = (const float*)d_in[3];  // [9]
    const float* dd  = (const float*)d_in[4];  // [8]
    const float* rho = (const float*)d_in[5];  // [1]
    float* out = (float*)d_out;                // [1,3,8,512,512] float32

    // opt in to >48KB dynamic shared memory for the staged solve
    // (host-side attribute, idempotent, not a stream op — capture-safe)
    cudaFuncSetAttribute(solve_kernel, cudaFuncAttributeMaxDynamicSharedMemorySize,
                         SOLVE_SMEM_BYTES);

    fill_tables<<<1, 512>>>(dd);

    // forward: paired row FFTs (2 real rows per complex FFT), then column FFTs
    fwd_rows_all<<<(NIMG_X + NIMG_Y) * (FFT_N / 8), 256>>>(x, y);
    fft_cols_fwd<<<dim3((NKX + 7) / 8, NIMG_X + NIMG_Y), 512>>>();

    // per-bin regularized least-squares solve (half spectrum, in-place)
    solve_kernel<<<NHBIN / 128, 128, SOLVE_SMEM_BYTES>>>(u, v, rho);

    // inverse: columns, then paired inverse row FFTs with Hermitian reconstruction
    fft_cols_inv<<<dim3((NKX + 7) / 8, NIMG_X), 512>>>();
    inv_rows<<<NIMG_X * (FFT_N / 8), 256>>>(out);
}

// round 16
// speedup vs baseline: 1.0289x; 1.0289x over previous
#include <cuda_runtime.h>
#include <cstdint>

#define FFT_N 512
#define NBIN (FFT_N * FFT_N)
#define N_C 3
#define N_K 8
#define N_V 9
#define NIMG_X (N_C * N_K)   // 24
#define NIMG_Y (N_C * N_V)   // 27
#define NKX 257              // half-spectrum columns kept (kx in [0,256])
#define NHBIN (FFT_N * NKX)  // 131584 half-spectrum bins
#define PI_F 3.14159265358979323846f

// column-FFT kernels: 8 slices * 1156 floats (stride ≡ 4 mod 32 -> conflict-free
// for the c = tid&7 interleave in all four exchange phases; 36.1KB static smem)
#define CSTRIDE8 1156

// ---------------- scratch (static device globals; no cudaMalloc allowed) ----
__device__ float2 d_Xs[(size_t)NIMG_X * NBIN];   // X spectrum, reused as FDL spectrum
__device__ float2 d_Ys[(size_t)NIMG_Y * NBIN];   // Y spectrum

// ---------------- complex helpers -------------------------------------------
__device__ __forceinline__ float2 cmulf2(float2 a, float2 b) {
    return make_float2(fmaf(a.x, b.x, -a.y * b.y), fmaf(a.x, b.y, a.y * b.x));
}
__device__ __forceinline__ float2 caddf2(float2 a, float2 b) { return make_float2(a.x + b.x, a.y + b.y); }
__device__ __forceinline__ float2 csubf2(float2 a, float2 b) { return make_float2(a.x - b.x, a.y - b.y); }
__device__ __forceinline__ float2 cconjf2(float2 a) { return make_float2(a.x, -a.y); }

__device__ __forceinline__ float2 cpowi(float2 z, float s) {
    if (s > 0.5f) return z;
    if (s < -0.5f) return cconjf2(z);
    return make_float2(1.f, 0.f);
}

// twiddle W512^j computed inline (same sincosf expression the old table used)
__device__ __forceinline__ float2 tw512(int j) {
    float s, c;
    sincosf(-2.f * PI_F * (float)j / (float)FFT_N, &s, &c);
    return make_float2(c, s);
}

// ---------------- packed f32x2 helpers (Blackwell FFMA2 via PTX) --------------
typedef unsigned long long u64p;
__device__ __forceinline__ u64p pk2(float x, float y) {
    u64p r; asm("mov.b64 %0, {%1, %2};" : "=l"(r) : "f"(x), "f"(y)); return r;
}
__device__ __forceinline__ u64p dup2(float s) { return pk2(s, s); }
__device__ __forceinline__ u64p fma2(u64p a, u64p b, u64p c) {
    u64p r; asm("fma.rn.f32x2 %0, %1, %2, %3;" : "=l"(r) : "l"(a), "l"(b), "l"(c)); return r;
}
__device__ __forceinline__ u64p mul2(u64p a, u64p b) {
    u64p r; asm("mul.rn.f32x2 %0, %1, %2;" : "=l"(r) : "l"(a), "l"(b)); return r;
}

// ---------------- register radix-8 butterflies --------------------------------
template <int INV>
__device__ __forceinline__ void fft4x(float2 v[4]) {
    float2 e0 = caddf2(v[0], v[2]), e1 = caddf2(v[1], v[3]);
    float2 o0 = csubf2(v[0], v[2]), o1 = csubf2(v[1], v[3]);
    o1 = INV ? make_float2(-o1.y, o1.x) : make_float2(o1.y, -o1.x);  // *(+-i)
    v[0] = caddf2(e0, e1); v[2] = csubf2(e0, e1);
    v[1] = caddf2(o0, o1); v[3] = csubf2(o0, o1);
}

template <int INV>
__device__ __forceinline__ void fft8(float2 a[8]) {
    const float C = 0.70710678118654752440f;
    float2 s[4], d[4];
#pragma unroll
    for (int k = 0; k < 4; k++) { s[k] = caddf2(a[k], a[k + 4]); d[k] = csubf2(a[k], a[k + 4]); }
    if (INV) {
        d[1] = cmulf2(d[1], make_float2(C, C));
        d[2] = make_float2(-d[2].y, d[2].x);
        d[3] = cmulf2(d[3], make_float2(-C, C));
    } else {
        d[1] = cmulf2(d[1], make_float2(C, -C));
        d[2] = make_float2(d[2].y, -d[2].x);
        d[3] = cmulf2(d[3], make_float2(-C, -C));
    }
    fft4x<INV>(s);
    fft4x<INV>(d);
    a[0] = s[0]; a[2] = s[1]; a[4] = s[2]; a[6] = s[3];
    a[1] = d[0]; a[3] = d[1]; a[5] = d[2]; a[7] = d[3];
}

// ---------------- 512-pt FFT: 64 threads, 8 regs, single-buffer (3 syncs) -----
// In:  a[j]  = x[t + 64*j],  t in [0,64)
// Out: a[m1] = X[t + 64*m1]
// Twiddles w1 = W512^t, w2 = W512^{8*(t&7)} computed by the caller (inline sincosf).
// Exchange A layout: [k0*72 + t]          Exchange B layout: [9*k0 + 72*m0 + r]
template <int INV>
__device__ __forceinline__ void fft512r8(float2 a[8], int t, float* re, float* im,
                                         float2 w1, float2 w2) {
    fft8<INV>(a);
    {   // a[k0] *= W512^{t*k0}
        float2 w = w1; if (INV) w.y = -w.y;
        float2 p = w;
#pragma unroll
        for (int k = 1; k < 8; k++) { a[k] = cmulf2(a[k], p); p = cmulf2(p, w); }
    }
#pragma unroll
    for (int k = 0; k < 8; k++) { re[k * 72 + t] = a[k].x; im[k * 72 + t] = a[k].y; }
    __syncthreads();
    int hi = t >> 3, lo = t & 7;
#pragma unroll
    for (int j = 0; j < 8; j++) {
        int idx = hi * 72 + 8 * j + lo;
        a[j] = make_float2(re[idx], im[idx]);
    }
    __syncthreads();                               // all reads done before overwrite
    fft8<INV>(a);
    {   // a[m0] *= W64^{lo*m0} = W512^{8*lo*m0}
        float2 w = w2; if (INV) w.y = -w.y;
        float2 p = w;
#pragma unroll
        for (int m = 1; m < 8; m++) { a[m] = cmulf2(a[m], p); p = cmulf2(p, w); }
    }
#pragma unroll
    for (int m = 0; m < 8; m++) {
        int idx = 9 * hi + 72 * m + lo;
        re[idx] = a[m].x; im[idx] = a[m].y;
    }
    __syncthreads();
#pragma unroll
    for (int r = 0; r < 8; r++) {
        int idx = 9 * lo + 72 * hi + r;
        a[r] = make_float2(re[idx], im[idx]);
    }
    fft8<INV>(a);
}

// ---------------- row FFT, PAIRED: two real rows per complex FFT --------------
// z = row(2p) + i*row(2p+1); A(k) = (Z(k)+conj(Z(-k)))/2, B(k) = (Z(k)-conj(Z(-k)))/2i.
// One block = 4 sub-FFTs = 4 row pairs = 8 rows. X and Y planes in one launch.
__global__ void fwd_rows_all(const float* __restrict__ xin, const float* __restrict__ yin) {
    __shared__ float s[4 * 1160];
    int blk = blockIdx.x;
    const float* in;
    float2* outp;
    if (blk < NIMG_X * (FFT_N / 8)) { in = xin; outp = d_Xs; }
    else { blk -= NIMG_X * (FFT_N / 8); in = yin; outp = d_Ys; }
    int sub = threadIdx.x >> 6;
    int t = threadIdx.x & 63;
    float2 w1 = tw512(t), w2 = tw512(8 * (t & 7));
    size_t pair = (size_t)blk * 4 + sub;           // row-pair index (512 rows/plane, 8|512)
    const float* src0 = in + pair * 2 * FFT_N;
    const float* src1 = src0 + FFT_N;
    float2* dst0 = outp + pair * 2 * FFT_N;
    float2* dst1 = dst0 + FFT_N;
    float2 a[8];
#pragma unroll
    for (int j = 0; j < 8; j++) a[j] = make_float2(src0[t + 64 * j], src1[t + 64 * j]);
    float* base = s + sub * 1160;
    fft512r8<0>(a, t, base, base + 576, w1, w2);
    // stash full Z in the (now free) exchange buffer for mirror access
    float2* zb = (float2*)base;                    // 580 c64 capacity >= 512
    __syncthreads();
#pragma unroll
    for (int m = 0; m < 8; m++) zb[t + 64 * m] = a[m];
    __syncthreads();
#pragma unroll
    for (int m = 0; m < 8; m++) {
        int k = t + 64 * m;
        if (k < NKX) {
            float2 Z = a[m];
            float2 Zm = zb[(512 - k) & 511];
            dst0[k] = make_float2(0.5f * (Z.x + Zm.x), 0.5f * (Z.y - Zm.y));   // A(k)
            dst1[k] = make_float2(0.5f * (Z.y + Zm.y), -0.5f * (Z.x - Zm.x));  // B(k)
        }
    }
}

// ---------------- forward column FFT: 8 columns per 512-thread block ----------
// Warp covers 8 consecutive kx x 4 rows = four full 128B lines per global op.
// 4 blocks/SM (36.1KB static smem), 16-warp barriers. X and Y in one launch.
__global__ void __launch_bounds__(512, 4) fft_cols_fwd(void) {
    __shared__ float s[8 * CSTRIDE8];
    int p = blockIdx.y;
    float2* data = (p < NIMG_X) ? d_Xs + (size_t)p * NBIN
                                : d_Ys + (size_t)(p - NIMG_X) * NBIN;
    int c = threadIdx.x & 7;
    int t = threadIdx.x >> 3;         // [0,64)
    float2 w1 = tw512(t), w2 = tw512(8 * (t & 7));
    int kx = blockIdx.x * 8 + c;
    bool act = (kx < NKX);
    float2* col = data + kx;
    float2 a[8];
#pragma unroll
    for (int j = 0; j < 8; j++)
        a[j] = act ? col[(size_t)(t + 64 * j) * FFT_N] : make_float2(0.f, 0.f);
    float* base = s + c * CSTRIDE8;
    fft512r8<0>(a, t, base, base + 576, w1, w2);
#pragma unroll
    for (int m = 0; m < 8; m++)
        if (act) col[(size_t)(t + 64 * m) * FFT_N] = a[m];
}

// ---------------- inverse column FFT (X planes), 8 columns/block --------------
__global__ void __launch_bounds__(512, 4) fft_cols_inv(void) {
    __shared__ float s[8 * CSTRIDE8];
    float2* data = d_Xs + (size_t)blockIdx.y * NBIN;
    int c = threadIdx.x & 7;
    int t = threadIdx.x >> 3;
    float2 w1 = tw512(t), w2 = tw512(8 * (t & 7));
    int kx = blockIdx.x * 8 + c;
    bool act = (kx < NKX);
    float2* col = data + kx;
    float2 a[8];
#pragma unroll
    for (int j = 0; j < 8; j++)
        a[j] = act ? col[(size_t)(t + 64 * j) * FFT_N] : make_float2(0.f, 0.f);
    float* base = s + c * CSTRIDE8;
    fft512r8<1>(a, t, base, base + 576, w1, w2);
#pragma unroll
    for (int m = 0; m < 8; m++)
        if (act) col[(size_t)(t + 64 * m) * FFT_N] = a[m];
}

// ---------------- inverse row FFT, PAIRED: two real rows per complex IFFT -----
__global__ void inv_rows(float* __restrict__ out) {
    __shared__ float s[4 * 1160];
    int sub = threadIdx.x >> 6;
    int t = threadIdx.x & 63;
    float2 w1 = tw512(t), w2 = tw512(8 * (t & 7));
    size_t pair = (size_t)blockIdx.x * 4 + sub;
    const float2* src0 = d_Xs + pair * 2 * FFT_N;
    const float2* src1 = src0 + FFT_N;
    float* dst0 = out + pair * 2 * FFT_N;
    float* dst1 = dst0 + FFT_N;
    float2 a[8];
#pragma unroll
    for (int j = 0; j < 8; j++) {
        int k = t + 64 * j;
        float2 Sa, Sb;
        if (k < NKX) {
            Sa = src0[k]; Sb = src1[k];
            if (k == 0 || k == 256) { Sa.y = 0.f; Sb.y = 0.f; }   // self-mirror cleanup
        } else {
            float2 ma = src0[512 - k], mb = src1[512 - k];
            Sa = make_float2(ma.x, -ma.y);
            Sb = make_float2(mb.x, -mb.y);
        }
        a[j] = make_float2(Sa.x - Sb.y, Sa.y + Sb.x);              // H_a + i*H_b
    }
    float* base = s + sub * 1160;
    fft512r8<1>(a, t, base, base + 576, w1, w2);
    const float sc = 1.f / (float)NBIN;
#pragma unroll
    for (int m = 0; m < 8; m++) {
        dst0[t + 64 * m] = a[m].x * sc;
        dst1[t + 64 * m] = a[m].y * sc;
    }
}

// ---------------- per-bin FDL solve (half spectrum, packed f32x2) --------------
// R12/R14 register version (best measured: 23.4us) with inline exponentials.
// One thread = one bin; all 3 channels batched (51-load MLP). Real Toeplitz Gram
// => one real Cholesky per bin.
// Row (ky==256, kx in [1,255]): conjugate y-exponentials, scale result by 0.5.
__global__ void __launch_bounds__(128, 4) solve_kernel(const float* __restrict__ up,
                                                       const float* __restrict__ vp,
                                                       const float* __restrict__ ddp,
                                                       const float* __restrict__ rhop) {
    int bidx = blockIdx.x * blockDim.x + threadIdx.x;   // half-spectrum bin index
    int ky = bidx / NKX;
    int kx = bidx - ky * NKX;
    int bin = ky * FFT_N + kx;
    float rho = rhop[0];
    float delta = ddp[1] - ddp[0];
    float d0 = ddp[0];

    // inline exponentials (same expressions the old fill_tables used)
    float cfx = (kx < FFT_N / 2) ? (float)kx : (float)(kx - FFT_N);
    float cfy = (ky < FFT_N / 2) ? (float)ky : (float)(ky - FFT_N);
    float wx = cfx * (2.f * PI_F / (float)FFT_N);
    float wy = cfy * (2.f * PI_F / (float)FFT_N);
    float2 Edx, E0x, Edy, E0y;
    sincosf(delta * wx, &Edx.y, &Edx.x);
    sincosf(-d0 * wx, &E0x.y, &E0x.x);
    sincosf(delta * wy, &Edy.y, &Edy.x);
    sincosf(-d0 * wy, &E0y.y, &E0y.x);

    bool mirror_row = (ky == 256 && kx >= 1 && kx <= 255);
    float hsc = mirror_row ? 0.5f : 1.0f;
    if (mirror_row) { Edy = cconjf2(Edy); E0y = cconjf2(E0y); }   // wy: -pi -> +pi

    // real Toeplitz generators t[m] = (1+2cos(m d wx))(1+2cos(m d wy))
    float tmr[8];
    {
        float axc = Edx.x, ayc = Edy.x;
        float cx1 = 1.f, cx = axc;
        float cy1 = 1.f, cy = ayc;
#pragma unroll
        for (int m = 1; m < 8; m++) {
            tmr[m] = (1.f + 2.f * cx) * (1.f + 2.f * cy);
            float nx = fmaf(2.f * axc, cx, -cx1); cx1 = cx; cx = nx;
            float ny = fmaf(2.f * ayc, cy, -cy1); cy1 = cy; cy = ny;
        }
    }

    // rhs = rho*X for all 3 channels (packed; 24 loads batched)
    u64p rhs[N_C][N_K];
    {
        u64p rho2 = dup2(rho);
#pragma unroll
        for (int c = 0; c < N_C; c++)
#pragma unroll
            for (int k = 0; k < N_K; k++) {
                u64p xv = *(const u64p*)&d_Xs[((size_t)(c * N_K + k)) * NBIN + bin];
                rhs[c][k] = mul2(xv, rho2);
            }
    }

    // accumulate A^H Y (27 loads per pass batched; FFMA2 pairs)
#pragma unroll
    for (int vi = 0; vi < N_V; vi++) {
        float uu = up[vi], vv = vp[vi];
        float2 e  = cmulf2(cpowi(Edx, uu), cpowi(Edy, vv));   // exp(+i*delta*s_v)
        float2 e0 = cmulf2(cpowi(E0x, uu), cpowi(E0y, vv));   // exp(-i*d0*s_v)
        float2 ec = cconjf2(e);

        u64p yp[N_C], ys[N_C];
#pragma unroll
        for (int c = 0; c < N_C; c++) {
            float2 yv = d_Ys[((size_t)(c * N_V + vi)) * NBIN + bin];
            yp[c] = pk2(yv.x, yv.y);
            ys[c] = pk2(-yv.y, yv.x);
        }

        float2 ak = e0;    // conj(A[v,k]) power chain (scalar)
#pragma unroll
        for (int k = 0; k < N_K; k++) {
            u64p axd = dup2(ak.x);
            u64p ayd = dup2(ak.y);
#pragma unroll
            for (int c = 0; c < N_C; c++)
                rhs[c][k] = fma2(axd, yp[c], fma2(ayd, ys[c], rhs[c][k]));
            ak = cmulf2(ak, ec);
        }
    }

    // real Cholesky of M (diag = 9 + rho, off-diag t[|k-l|]) -- once per bin
    float L[8][8];
    float di[8];
#pragma unroll
    for (int l = 0; l < 8; l++) {
        float ds = (float)N_V + rho;
#pragma unroll
        for (int j = 0; j < l; j++) ds = fmaf(-L[l][j], L[l][j], ds);
        float inv = rsqrtf(ds);
        di[l] = inv;
#pragma unroll
        for (int k = l + 1; k < 8; k++) {
            float s = tmr[k - l];
#pragma unroll
            for (int j = 0; j < l; j++) s = fmaf(-L[k][j], L[l][j], s);
            L[k][l] = s * inv;
        }
    }

    // forward substitution (channel-inner: dup(-L) shared across channels)
#pragma unroll
    for (int l = 0; l < 8; l++) {
#pragma unroll
        for (int j = 0; j < l; j++) {
            u64p Ld = dup2(-L[l][j]);
#pragma unroll
            for (int c = 0; c < N_C; c++)
                rhs[c][l] = fma2(Ld, rhs[c][j], rhs[c][l]);
        }
        u64p dd = dup2(di[l]);
#pragma unroll
        for (int c = 0; c < N_C; c++) rhs[c][l] = mul2(rhs[c][l], dd);
    }
    // back substitution
#pragma unroll
    for (int k = 7; k >= 0; k--) {
#pragma unroll
        for (int j = k + 1; j < 8; j++) {
            u64p Ld = dup2(-L[j][k]);
#pragma unroll
            for (int c = 0; c < N_C; c++)
                rhs[c][k] = fma2(Ld, rhs[c][j], rhs[c][k]);
        }
        u64p dd = dup2(di[k]);
#pragma unroll
        for (int c = 0; c < N_C; c++) rhs[c][k] = mul2(rhs[c][k], dd);
    }

    // store with mirror-row half-weight
    u64p hd = dup2(hsc);
#pragma unroll
    for (int c = 0; c < N_C; c++)
#pragma unroll
        for (int k = 0; k < N_K; k++)
            *(u64p*)&d_Xs[((size_t)(c * N_K + k)) * NBIN + bin] = mul2(rhs[c][k], hd);
}

// ---------------- launch ------------------------------------------------------
extern "C" void kernel_launch(void* const* d_in, const int* in_sizes, int n_in,
                              void* d_out, int out_size) {
    const float* x   = (const float*)d_in[0];  // [1,3,8,512,512]
    const float* y   = (const float*)d_in[1];  // [1,3,9,512,512]
    const float* u   = (const float*)d_in[2];  // [9]
    const float* v   = (const float*)d_in[3];  // [9]
    const float* dd  = (const float*)d_in[4];  // [8]
    const float* rho = (const float*)d_in[5];  // [1]
    float* out = (float*)d_out;                // [1,3,8,512,512] float32

    // forward: paired row FFTs (2 real rows per complex FFT), then column FFTs
    fwd_rows_all<<<(NIMG_X + NIMG_Y) * (FFT_N / 8), 256>>>(x, y);
    fft_cols_fwd<<<dim3((NKX + 7) / 8, NIMG_X + NIMG_Y), 512>>>();

    // per-bin regularized least-squares solve (half spectrum, in-place)
    solve_kernel<<<NHBIN / 128, 128>>>(u, v, dd, rho);

    // inverse: columns, then paired inverse row FFTs with Hermitian reconstruction
    fft_cols_inv<<<dim3((NKX + 7) / 8, NIMG_X), 512>>>();
    inv_rows<<<NIMG_X * (FFT_N / 8), 256>>>(out);
}